// round 1
// baseline (speedup 1.0000x reference)
#include <cuda_runtime.h>
#include <math.h>

// ---------------------------------------------------------------------------
// CenterRingFormerPlus: 7-GEMM chain + cluster softmax, fp32 baseline.
// M = B*N = 16384 rows, all GEMM output widths = 1024.
// ---------------------------------------------------------------------------

#define M_TOT 16384
#define N_TOT 1024
#define BM 128
#define BN 128
#define BK 8

// Scratch (device globals; no allocation allowed in kernel_launch)
__device__ float g_h1     [16384u * 1024u];
__device__ float g_xring  [16384u * 1024u];
__device__ float g_t1     [16384u * 1024u];
__device__ float g_tproj  [16384u * 1024u];
__device__ float g_wtd    [16384u * 1024u];
__device__ float g_gate   [16384u * 1024u];
__device__ float g_hfc    [16384u * 1024u];

__constant__ int c_shifts[7] = {1, -1, 0, 2, -2, 4, -4};

enum { ASRC_DIRECT = 0, ASRC_ROLL = 1, ASRC_CONCAT = 2 };
enum { EPI_NONE = 0, EPI_GELU = 1, EPI_SIGMOID = 2, EPI_FINAL = 3 };

__device__ __forceinline__ float gelu_exact(float x) {
    // jax.nn.gelu(approximate=False) == x * 0.5 * (1 + erf(x/sqrt(2)))
    return 0.5f * x * (1.0f + erff(x * 0.7071067811865476f));
}

// ---------------------------------------------------------------------------
// Tiled SGEMM: C[M_TOT, 1024] = epi(A @ Bw + bias)
//   ASRC_DIRECT: A is [M_TOT, K] row-major, lda = K
//   ASRC_ROLL  : A is queries [8, 2048, 1024]; logical K = 7168, the k-block
//                s = k/1024 reads row (n - shift[s]) mod 2048 of the same batch
//   ASRC_CONCAT: logical K = 2048; k<1024 from A (x_ring), else A2 (weighted)
// ---------------------------------------------------------------------------
template <int ASRC, int EPI>
__global__ __launch_bounds__(256, 2)
void gemm_k(const float* __restrict__ A, const float* __restrict__ A2,
            const float* __restrict__ Bw, const float* __restrict__ bias,
            float* __restrict__ C, int K,
            const float* __restrict__ e_gate, const float* __restrict__ e_xring)
{
    __shared__ float As[BK][BM];
    __shared__ float Bs[BK][BN];

    const int tid = threadIdx.x;
    const int bm = blockIdx.y * BM;
    const int bn = blockIdx.x * BN;

    // A-tile load mapping: 128 rows x 8 k, float4 per thread
    const int arow = tid >> 1;           // 0..127
    const int acol = (tid & 1) * 4;      // 0 or 4
    // B-tile load mapping: 8 rows x 128 cols, float4 per thread
    const int brow = tid >> 5;           // 0..7
    const int bcol = (tid & 31) * 4;

    const int tx = tid & 15;             // col group (8 cols each)
    const int ty = tid >> 4;             // row group (8 rows each)

    const int m_g = bm + arow;           // global A row for loads
    const int bb = m_g >> 11;            // batch (for ROLL)
    const int nn = m_g & 2047;           // seq pos (for ROLL)

    float acc[8][8];
#pragma unroll
    for (int i = 0; i < 8; i++)
#pragma unroll
        for (int j = 0; j < 8; j++) acc[i][j] = 0.0f;

    for (int k0 = 0; k0 < K; k0 += BK) {
        // ---- load A tile (transposed into As[k][m]) ----
        float4 av;
        if (ASRC == ASRC_DIRECT) {
            av = *(const float4*)(A + (size_t)m_g * K + (k0 + acol));
        } else if (ASRC == ASRC_ROLL) {
            const int s = k0 >> 10;                 // which shift block
            const int d0 = (k0 & 1023) + acol;      // col within D
            const int src = (nn - c_shifts[s]) & 2047;
            av = *(const float4*)(A + ((size_t)((bb << 11) | src)) * 1024u + d0);
        } else {  // ASRC_CONCAT
            const float* src = (k0 < 1024) ? A : A2;
            const int d0 = (k0 & 1023) + acol;
            av = *(const float4*)(src + (size_t)m_g * 1024u + d0);
        }
        As[acol + 0][arow] = av.x;
        As[acol + 1][arow] = av.y;
        As[acol + 2][arow] = av.z;
        As[acol + 3][arow] = av.w;

        // ---- load B tile ----
        float4 bv = *(const float4*)(Bw + (size_t)(k0 + brow) * N_TOT + (bn + bcol));
        *(float4*)(&Bs[brow][bcol]) = bv;

        __syncthreads();

#pragma unroll
        for (int kk = 0; kk < BK; kk++) {
            float a[8], b[8];
            *(float4*)&a[0] = *(const float4*)&As[kk][ty * 8];
            *(float4*)&a[4] = *(const float4*)&As[kk][ty * 8 + 4];
            *(float4*)&b[0] = *(const float4*)&Bs[kk][tx * 8];
            *(float4*)&b[4] = *(const float4*)&Bs[kk][tx * 8 + 4];
#pragma unroll
            for (int i = 0; i < 8; i++)
#pragma unroll
                for (int j = 0; j < 8; j++)
                    acc[i][j] = fmaf(a[i], b[j], acc[i][j]);
        }
        __syncthreads();
    }

    // ---- epilogue ----
#pragma unroll
    for (int i = 0; i < 8; i++) {
        const int m = bm + ty * 8 + i;
#pragma unroll
        for (int j = 0; j < 8; j++) {
            const int n = bn + tx * 8 + j;
            float v = acc[i][j] + bias[n];
            if (EPI == EPI_GELU) {
                v = gelu_exact(v);
            } else if (EPI == EPI_SIGMOID) {
                v = 1.0f / (1.0f + expf(-v));
            } else if (EPI == EPI_FINAL) {
                const size_t idx = (size_t)m * 1024u + n;
                const float g = e_gate[idx];
                v = g * v + (1.0f - g) * e_xring[idx];
            }
            C[(size_t)m * N_TOT + n] = v;
        }
    }
}

// ---------------------------------------------------------------------------
// Cluster softmax: logits = tproj @ centers^T (K=4), softmax, weighted = w@centers
// 1 warp per row; centers (4x1024 = 16KB) staged in smem.
// ---------------------------------------------------------------------------
__global__ __launch_bounds__(256)
void cluster_k(const float* __restrict__ tproj, const float* __restrict__ centers,
               float* __restrict__ weighted)
{
    __shared__ float sc[4 * 1024];
    const int tid = threadIdx.x;
    for (int i = tid * 4; i < 4096; i += 256 * 4)
        *(float4*)&sc[i] = *(const float4*)&centers[i];
    __syncthreads();

    const int warp = tid >> 5;
    const int lane = tid & 31;
    const size_t row = (size_t)blockIdx.x * 8 + warp;
    const float* tp = tproj + row * 1024u;

    float d0 = 0.f, d1 = 0.f, d2 = 0.f, d3 = 0.f;
    for (int d = lane * 4; d < 1024; d += 128) {
        float4 t  = *(const float4*)(tp + d);
        float4 c0 = *(const float4*)(sc + d);
        float4 c1 = *(const float4*)(sc + 1024 + d);
        float4 c2 = *(const float4*)(sc + 2048 + d);
        float4 c3 = *(const float4*)(sc + 3072 + d);
        d0 += t.x * c0.x + t.y * c0.y + t.z * c0.z + t.w * c0.w;
        d1 += t.x * c1.x + t.y * c1.y + t.z * c1.z + t.w * c1.w;
        d2 += t.x * c2.x + t.y * c2.y + t.z * c2.z + t.w * c2.w;
        d3 += t.x * c3.x + t.y * c3.y + t.z * c3.z + t.w * c3.w;
    }
#pragma unroll
    for (int off = 16; off > 0; off >>= 1) {
        d0 += __shfl_xor_sync(0xffffffffu, d0, off);
        d1 += __shfl_xor_sync(0xffffffffu, d1, off);
        d2 += __shfl_xor_sync(0xffffffffu, d2, off);
        d3 += __shfl_xor_sync(0xffffffffu, d3, off);
    }
    const float mx = fmaxf(fmaxf(d0, d1), fmaxf(d2, d3));
    const float e0 = expf(d0 - mx), e1 = expf(d1 - mx),
                e2 = expf(d2 - mx), e3 = expf(d3 - mx);
    const float inv = 1.0f / (e0 + e1 + e2 + e3);
    const float w0 = e0 * inv, w1 = e1 * inv, w2 = e2 * inv, w3 = e3 * inv;

    float* out = weighted + row * 1024u;
    for (int d = lane * 4; d < 1024; d += 128) {
        float4 c0 = *(const float4*)(sc + d);
        float4 c1 = *(const float4*)(sc + 1024 + d);
        float4 c2 = *(const float4*)(sc + 2048 + d);
        float4 c3 = *(const float4*)(sc + 3072 + d);
        float4 o;
        o.x = w0 * c0.x + w1 * c1.x + w2 * c2.x + w3 * c3.x;
        o.y = w0 * c0.y + w1 * c1.y + w2 * c2.y + w3 * c3.y;
        o.z = w0 * c0.z + w1 * c1.z + w2 * c2.z + w3 * c3.z;
        o.w = w0 * c0.w + w1 * c1.w + w2 * c2.w + w3 * c3.w;
        *(float4*)(out + d) = o;
    }
}

// ---------------------------------------------------------------------------
// Launch
// ---------------------------------------------------------------------------
extern "C" void kernel_launch(void* const* d_in, const int* in_sizes, int n_in,
                              void* d_out, int out_size)
{
    const float* queries = (const float*)d_in[0];
    const float* fr_w1   = (const float*)d_in[1];
    const float* fr_b1   = (const float*)d_in[2];
    const float* fr_w2   = (const float*)d_in[3];
    const float* fr_b2   = (const float*)d_in[4];
    const float* tc_w1   = (const float*)d_in[5];
    const float* tc_b1   = (const float*)d_in[6];
    const float* tc_w2   = (const float*)d_in[7];
    const float* tc_b2   = (const float*)d_in[8];
    const float* centers = (const float*)d_in[9];
    const float* fc_w1   = (const float*)d_in[10];
    const float* fc_b1   = (const float*)d_in[11];
    const float* fc_w2   = (const float*)d_in[12];
    const float* fc_b2   = (const float*)d_in[13];
    const float* g_w     = (const float*)d_in[14];
    const float* g_b     = (const float*)d_in[15];
    float* out = (float*)d_out;

    float *h1, *xr, *t1, *tp, *wt, *gt, *hfc;
    cudaGetSymbolAddress((void**)&h1,  g_h1);
    cudaGetSymbolAddress((void**)&xr,  g_xring);
    cudaGetSymbolAddress((void**)&t1,  g_t1);
    cudaGetSymbolAddress((void**)&tp,  g_tproj);
    cudaGetSymbolAddress((void**)&wt,  g_wtd);
    cudaGetSymbolAddress((void**)&gt,  g_gate);
    cudaGetSymbolAddress((void**)&hfc, g_hfc);

    dim3 grid(N_TOT / BN, M_TOT / BM);   // (8, 128)
    dim3 block(256);

    // 1) h1 = gelu(fusion @ fr_w1 + fr_b1), fusion gathered on the fly (K=7168)
    gemm_k<ASRC_ROLL, EPI_GELU><<<grid, block>>>(
        queries, nullptr, fr_w1, fr_b1, h1, 7168, nullptr, nullptr);
    // 2) x_ring = h1 @ fr_w2 + fr_b2
    gemm_k<ASRC_DIRECT, EPI_NONE><<<grid, block>>>(
        h1, nullptr, fr_w2, fr_b2, xr, 1024, nullptr, nullptr);
    // 3) t1 = gelu(x_ring @ tc_w1 + tc_b1)
    gemm_k<ASRC_DIRECT, EPI_GELU><<<grid, block>>>(
        xr, nullptr, tc_w1, tc_b1, t1, 1024, nullptr, nullptr);
    // 4) token_proj = t1 @ tc_w2 + tc_b2
    gemm_k<ASRC_DIRECT, EPI_NONE><<<grid, block>>>(
        t1, nullptr, tc_w2, tc_b2, tp, 1024, nullptr, nullptr);
    // 5) weighted = softmax(token_proj @ centers^T) @ centers
    cluster_k<<<M_TOT / 8, 256>>>(tp, centers, wt);
    // 6) gate = sigmoid([x_ring|weighted] @ g_w + g_b)   (K=2048)
    gemm_k<ASRC_CONCAT, EPI_SIGMOID><<<grid, block>>>(
        xr, wt, g_w, g_b, gt, 2048, nullptr, nullptr);
    // 7) h_fc = gelu([x_ring|weighted] @ fc_w1 + fc_b1)  (K=2048)
    gemm_k<ASRC_CONCAT, EPI_GELU><<<grid, block>>>(
        xr, wt, fc_w1, fc_b1, hfc, 2048, nullptr, nullptr);
    // 8) out = gate * (h_fc @ fc_w2 + fc_b2) + (1-gate) * x_ring
    gemm_k<ASRC_DIRECT, EPI_FINAL><<<grid, block>>>(
        hfc, nullptr, fc_w2, fc_b2, out, 1024, gt, xr);
}

// round 4
// speedup vs baseline: 3.8563x; 3.8563x over previous
#include <cuda_runtime.h>
#include <cuda_bf16.h>
#include <cstdint>
#include <math.h>

// ---------------------------------------------------------------------------
// CenterRingFormerPlus via HMMA (mma.sync bf16, hi/lo split 3-MMA for accuracy)
// 128x128 CTA tile, BK=64 stages, 3-stage cp.async ring, SW128 swizzle,
// register accumulators, fused epilogues. (tcgen05 unavailable: harness
// compiles to family target sm_103, not sm_103a.)
// ---------------------------------------------------------------------------

#define MT 16384
#define NT 1024
#define NELE (16384u * 1024u)

// ---- scratch (device globals; no allocation allowed) ----
__device__ __nv_bfloat16 g_qh[NELE],  g_ql[NELE];
__device__ __nv_bfloat16 g_h1h[NELE], g_h1l[NELE];
__device__ __nv_bfloat16 g_xrh[NELE], g_xrl[NELE];
__device__ __nv_bfloat16 g_t1h[NELE], g_t1l[NELE];
__device__ __nv_bfloat16 g_wth[NELE], g_wtl[NELE];
__device__ __nv_bfloat16 g_hfh[NELE], g_hfl[NELE];
__device__ float g_xrf[NELE];
__device__ float g_tpf[NELE];
__device__ float g_gtf[NELE];
// transposed weights, [N=1024, K] K-major, hi/lo bf16
__device__ __nv_bfloat16 g_w1th[1024u*7168u], g_w1tl[1024u*7168u];
__device__ __nv_bfloat16 g_w2th[1024u*1024u], g_w2tl[1024u*1024u];
__device__ __nv_bfloat16 g_c1th[1024u*1024u], g_c1tl[1024u*1024u];
__device__ __nv_bfloat16 g_c2th[1024u*1024u], g_c2tl[1024u*1024u];
__device__ __nv_bfloat16 g_f2th[1024u*1024u], g_f2tl[1024u*1024u];
__device__ __nv_bfloat16 g_fcth[1024u*2048u], g_fctl[1024u*2048u];
__device__ __nv_bfloat16 g_gwth[1024u*2048u], g_gwtl[1024u*2048u];

__constant__ int c_shifts[7] = {1, -1, 0, 2, -2, 4, -4};

enum { A_DIRECT = 0, A_ROLL = 1, A_CONCAT = 2 };
enum { EP_GELU_BF = 0, EP_BF_F32 = 1, EP_F32 = 2, EP_SIG = 3, EP_FINAL = 4 };

// ---------------- helpers ----------------
static __device__ __forceinline__ uint32_t s2u(const void* p) {
    return (uint32_t)__cvta_generic_to_shared(p);
}
static __device__ __forceinline__ void cp16(uint32_t d, const void* s) {
    asm volatile("cp.async.cg.shared.global [%0], [%1], 16;\n" :: "r"(d), "l"(s));
}
static __device__ __forceinline__ void cp_commit() {
    asm volatile("cp.async.commit_group;\n" ::: "memory");
}
static __device__ __forceinline__ void ldm4(uint32_t& r0, uint32_t& r1,
                                            uint32_t& r2, uint32_t& r3, uint32_t a) {
    asm volatile("ldmatrix.sync.aligned.m8n8.x4.shared.b16 {%0,%1,%2,%3}, [%4];"
                 : "=r"(r0), "=r"(r1), "=r"(r2), "=r"(r3) : "r"(a));
}
static __device__ __forceinline__ void mma16816(float* d, const uint32_t* a,
                                                const uint32_t* b) {
    asm volatile(
        "mma.sync.aligned.m16n8k16.row.col.f32.bf16.bf16.f32 "
        "{%0,%1,%2,%3}, {%4,%5,%6,%7}, {%8,%9}, {%0,%1,%2,%3};"
        : "+f"(d[0]), "+f"(d[1]), "+f"(d[2]), "+f"(d[3])
        : "r"(a[0]), "r"(a[1]), "r"(a[2]), "r"(a[3]), "r"(b[0]), "r"(b[1]));
}
static __device__ __forceinline__ float gelu_exact(float x) {
    return 0.5f * x * (1.0f + erff(x * 0.7071067811865476f));
}
static __device__ __forceinline__ void split_bf(float v, __nv_bfloat16& h, __nv_bfloat16& l) {
    h = __float2bfloat16(v);
    l = __float2bfloat16(v - __bfloat162float(h));
}

// ---------------- tile loader (BK=64, SW128 swizzle, hi/lo A and B) --------
#define STG_BYTES 65536
#define T_AH 0
#define T_AL 16384
#define T_BH 32768
#define T_BL 49152

template <int ASRC>
static __device__ __forceinline__ void load_stage(
    uint32_t buf,
    const __nv_bfloat16* __restrict__ Ah, const __nv_bfloat16* __restrict__ Al,
    const __nv_bfloat16* __restrict__ A2h, const __nv_bfloat16* __restrict__ A2l,
    const __nv_bfloat16* __restrict__ Bh, const __nv_bfloat16* __restrict__ Bl,
    int K, int k0, int bm, int bn, int tid)
{
#pragma unroll
    for (int i = 0; i < 4; i++) {
        const int c = tid + i * 256;
        const int r = c >> 3, ch = c & 7;
        const uint32_t bo = (uint32_t)(r * 128 + ch * 16);
        const uint32_t sw = bo ^ ((bo >> 3) & 0x70);

        const __nv_bfloat16 *pah, *pal;
        size_t aoff;
        if (ASRC == A_DIRECT) {
            aoff = (size_t)(bm + r) * (size_t)K + (size_t)(k0 + ch * 8);
            pah = Ah; pal = Al;
        } else if (ASRC == A_ROLL) {
            const int sh = c_shifts[k0 >> 10];
            const int m = bm + r, bb = m >> 11, nn = m & 2047;
            const int src = (nn - sh) & 2047;
            aoff = ((size_t)((bb << 11) | src)) * 1024u + (size_t)((k0 & 1023) + ch * 8);
            pah = Ah; pal = Al;
        } else {
            if (k0 < 1024) { pah = Ah; pal = Al; } else { pah = A2h; pal = A2l; }
            aoff = (size_t)(bm + r) * 1024u + (size_t)((k0 & 1023) + ch * 8);
        }
        cp16(buf + T_AH + sw, pah + aoff);
        cp16(buf + T_AL + sw, pal + aoff);

        const size_t boff = (size_t)(bn + r) * (size_t)K + (size_t)(k0 + ch * 8);
        cp16(buf + T_BH + sw, Bh + boff);
        cp16(buf + T_BL + sw, Bl + boff);
    }
}

// ---------------- main GEMM kernel ----------------
#define SMEM_DYN (1024 + 3 * STG_BYTES)

template <int ASRC, int EPI>
__global__ __launch_bounds__(256, 1)
void mm_k(const __nv_bfloat16* __restrict__ Ah, const __nv_bfloat16* __restrict__ Al,
          const __nv_bfloat16* __restrict__ A2h, const __nv_bfloat16* __restrict__ A2l,
          const __nv_bfloat16* __restrict__ Bth, const __nv_bfloat16* __restrict__ Btl,
          const float* __restrict__ bias, int K,
          __nv_bfloat16* __restrict__ Oh, __nv_bfloat16* __restrict__ Ol,
          float* __restrict__ Of,
          const float* __restrict__ e_gate, const float* __restrict__ e_xr)
{
    extern __shared__ char smraw[];
    const uint32_t bufbase = (s2u(smraw) + 1023u) & ~1023u;
    const int tid = threadIdx.x, wid = tid >> 5, lane = tid & 31;
    const int bn = blockIdx.x * 128, bm = blockIdx.y * 128;

    const int wm = (wid >> 2) * 64;   // warp row offset (0 or 64)
    const int wn = (wid & 3) * 32;    // warp col offset (0,32,64,96)

    float acc[4][4][4];
#pragma unroll
    for (int mt = 0; mt < 4; mt++)
#pragma unroll
        for (int nt = 0; nt < 4; nt++)
#pragma unroll
            for (int r = 0; r < 4; r++) acc[mt][nt][r] = 0.0f;

    const int nst = K >> 6;

    // prologue: stages 0 and 1
    load_stage<ASRC>(bufbase,             Ah, Al, A2h, A2l, Bth, Btl, K, 0,  bm, bn, tid);
    cp_commit();
    load_stage<ASRC>(bufbase + STG_BYTES, Ah, Al, A2h, A2l, Bth, Btl, K, 64, bm, bn, tid);
    cp_commit();

    // per-thread ldmatrix address components (within-tile byte offsets)
    const int a_row = lane & 15;            // row within 16
    const int a_kb  = ((lane >> 4) & 1) * 16;
    const int b_row = (lane & 7) + ((lane >> 4) & 1) * 8;
    const int b_kb  = ((lane >> 3) & 1) * 16;

    for (int s = 0; s < nst; s++) {
        if (s + 2 < nst) {
            load_stage<ASRC>(bufbase + (uint32_t)((s + 2) % 3) * STG_BYTES,
                             Ah, Al, A2h, A2l, Bth, Btl, K, (s + 2) * 64, bm, bn, tid);
            cp_commit();
        }
        const int rem = nst - 1 - s;
        if (rem >= 2)      asm volatile("cp.async.wait_group 2;" ::: "memory");
        else if (rem == 1) asm volatile("cp.async.wait_group 1;" ::: "memory");
        else               asm volatile("cp.async.wait_group 0;" ::: "memory");
        __syncthreads();

        const uint32_t buf = bufbase + (uint32_t)(s % 3) * STG_BYTES;
#pragma unroll
        for (int kk = 0; kk < 4; kk++) {
            // B fragments: 4 n-tiles, hi and lo
            uint32_t bh[4][2], bl[4][2];
#pragma unroll
            for (int p = 0; p < 2; p++) {
                const uint32_t bo =
                    (uint32_t)((wn + p * 16 + b_row) * 128 + kk * 32 + b_kb);
                const uint32_t sw = bo ^ ((bo >> 3) & 0x70);
                ldm4(bh[2*p][0], bh[2*p][1], bh[2*p+1][0], bh[2*p+1][1], buf + T_BH + sw);
                ldm4(bl[2*p][0], bl[2*p][1], bl[2*p+1][0], bl[2*p+1][1], buf + T_BL + sw);
            }
#pragma unroll
            for (int mt = 0; mt < 4; mt++) {
                const uint32_t bo =
                    (uint32_t)((wm + mt * 16 + a_row) * 128 + kk * 32 + a_kb);
                const uint32_t sw = bo ^ ((bo >> 3) & 0x70);
                uint32_t ah[4], al[4];
                ldm4(ah[0], ah[1], ah[2], ah[3], buf + T_AH + sw);
                ldm4(al[0], al[1], al[2], al[3], buf + T_AL + sw);
#pragma unroll
                for (int nt = 0; nt < 4; nt++) {
                    mma16816(acc[mt][nt], ah, bh[nt]);
                    mma16816(acc[mt][nt], ah, bl[nt]);
                    mma16816(acc[mt][nt], al, bh[nt]);
                }
            }
        }
        __syncthreads();
    }

    // ---- epilogue (register accumulators, fused) ----
    const int qr = lane >> 2;           // 0..7
    const int qc = (lane & 3) * 2;      // 0,2,4,6
#pragma unroll
    for (int mt = 0; mt < 4; mt++) {
#pragma unroll
        for (int nt = 0; nt < 4; nt++) {
            const int col = bn + wn + nt * 8 + qc;
            const float2 bs = *(const float2*)(bias + col);
#pragma unroll
            for (int h = 0; h < 2; h++) {
                const int row = bm + wm + mt * 16 + qr + h * 8;
                const size_t off = (size_t)row * 1024u + (size_t)col;
                float v0 = acc[mt][nt][2*h]     + bs.x;
                float v1 = acc[mt][nt][2*h + 1] + bs.y;

                if (EPI == EP_GELU_BF) {
                    v0 = gelu_exact(v0);  v1 = gelu_exact(v1);
                    __nv_bfloat162 hh, ll;
                    split_bf(v0, hh.x, ll.x);  split_bf(v1, hh.y, ll.y);
                    *(__nv_bfloat162*)(Oh + off) = hh;
                    *(__nv_bfloat162*)(Ol + off) = ll;
                } else if (EPI == EP_BF_F32) {
                    __nv_bfloat162 hh, ll;
                    split_bf(v0, hh.x, ll.x);  split_bf(v1, hh.y, ll.y);
                    *(__nv_bfloat162*)(Oh + off) = hh;
                    *(__nv_bfloat162*)(Ol + off) = ll;
                    *(float2*)(Of + off) = make_float2(v0, v1);
                } else if (EPI == EP_F32) {
                    *(float2*)(Of + off) = make_float2(v0, v1);
                } else if (EPI == EP_SIG) {
                    v0 = 1.0f / (1.0f + expf(-v0));
                    v1 = 1.0f / (1.0f + expf(-v1));
                    *(float2*)(Of + off) = make_float2(v0, v1);
                } else {  // EP_FINAL
                    const float2 g = *(const float2*)(e_gate + off);
                    const float2 x = *(const float2*)(e_xr + off);
                    *(float2*)(Of + off) = make_float2(
                        g.x * v0 + (1.0f - g.x) * x.x,
                        g.y * v1 + (1.0f - g.y) * x.y);
                }
            }
        }
    }
}

// ---------------- weight transpose-convert: W[K,N] f32 -> Th/Tl[N,K] bf16 ----
__global__ void wconv_k(const float* __restrict__ W, __nv_bfloat16* __restrict__ Th,
                        __nv_bfloat16* __restrict__ Tl, int K, int N)
{
    __shared__ float t[32][33];
    const int n0 = blockIdx.x * 32, k0 = blockIdx.y * 32;
    const int tx = threadIdx.x, ty = threadIdx.y;
#pragma unroll
    for (int i = 0; i < 4; i++)
        t[ty + i * 8][tx] = W[(size_t)(k0 + ty + i * 8) * N + n0 + tx];
    __syncthreads();
#pragma unroll
    for (int i = 0; i < 4; i++) {
        const float v = t[tx][ty + i * 8];
        __nv_bfloat16 h, l;
        split_bf(v, h, l);
        const size_t o = (size_t)(n0 + ty + i * 8) * K + k0 + tx;
        Th[o] = h;  Tl[o] = l;
    }
}

// ---------------- queries convert ----------------
__global__ void qconv_k(const float* __restrict__ Q, __nv_bfloat16* __restrict__ Hh,
                        __nv_bfloat16* __restrict__ Hl, int n)
{
    for (int i = blockIdx.x * 256 + threadIdx.x; i < n; i += gridDim.x * 256) {
        __nv_bfloat16 h, l;
        split_bf(Q[i], h, l);
        Hh[i] = h;  Hl[i] = l;
    }
}

// ---------------- cluster softmax ----------------
__global__ __launch_bounds__(256)
void cluster_k(const float* __restrict__ tproj, const float* __restrict__ centers,
               __nv_bfloat16* __restrict__ wh, __nv_bfloat16* __restrict__ wl)
{
    __shared__ float sc[4 * 1024];
    const int tid = threadIdx.x;
    for (int i = tid * 4; i < 4096; i += 256 * 4)
        *(float4*)&sc[i] = *(const float4*)&centers[i];
    __syncthreads();

    const int warp = tid >> 5, lane = tid & 31;
    const size_t row = (size_t)blockIdx.x * 8 + warp;
    const float* tp = tproj + row * 1024u;

    float d0 = 0.f, d1 = 0.f, d2 = 0.f, d3 = 0.f;
    for (int d = lane * 4; d < 1024; d += 128) {
        float4 t  = *(const float4*)(tp + d);
        float4 c0 = *(const float4*)(sc + d);
        float4 c1 = *(const float4*)(sc + 1024 + d);
        float4 c2 = *(const float4*)(sc + 2048 + d);
        float4 c3 = *(const float4*)(sc + 3072 + d);
        d0 += t.x*c0.x + t.y*c0.y + t.z*c0.z + t.w*c0.w;
        d1 += t.x*c1.x + t.y*c1.y + t.z*c1.z + t.w*c1.w;
        d2 += t.x*c2.x + t.y*c2.y + t.z*c2.z + t.w*c2.w;
        d3 += t.x*c3.x + t.y*c3.y + t.z*c3.z + t.w*c3.w;
    }
#pragma unroll
    for (int off = 16; off > 0; off >>= 1) {
        d0 += __shfl_xor_sync(0xffffffffu, d0, off);
        d1 += __shfl_xor_sync(0xffffffffu, d1, off);
        d2 += __shfl_xor_sync(0xffffffffu, d2, off);
        d3 += __shfl_xor_sync(0xffffffffu, d3, off);
    }
    const float mx = fmaxf(fmaxf(d0, d1), fmaxf(d2, d3));
    const float e0 = expf(d0 - mx), e1 = expf(d1 - mx),
                e2 = expf(d2 - mx), e3 = expf(d3 - mx);
    const float inv = 1.0f / (e0 + e1 + e2 + e3);
    const float w0 = e0*inv, w1 = e1*inv, w2 = e2*inv, w3 = e3*inv;

    for (int d = lane * 4; d < 1024; d += 128) {
        float4 c0 = *(const float4*)(sc + d);
        float4 c1 = *(const float4*)(sc + 1024 + d);
        float4 c2 = *(const float4*)(sc + 2048 + d);
        float4 c3 = *(const float4*)(sc + 3072 + d);
        float o[4];
        o[0] = w0*c0.x + w1*c1.x + w2*c2.x + w3*c3.x;
        o[1] = w0*c0.y + w1*c1.y + w2*c2.y + w3*c3.y;
        o[2] = w0*c0.z + w1*c1.z + w2*c2.z + w3*c3.z;
        o[3] = w0*c0.w + w1*c1.w + w2*c2.w + w3*c3.w;
        __nv_bfloat162 h2[2], l2[2];
#pragma unroll
        for (int p = 0; p < 2; p++) {
            split_bf(o[2*p],   h2[p].x, l2[p].x);
            split_bf(o[2*p+1], h2[p].y, l2[p].y);
        }
        *(uint2*)(wh + row * 1024u + d) = *(uint2*)h2;
        *(uint2*)(wl + row * 1024u + d) = *(uint2*)l2;
    }
}

// ---------------- launch ----------------
extern "C" void kernel_launch(void* const* d_in, const int* in_sizes, int n_in,
                              void* d_out, int out_size)
{
    const float* queries = (const float*)d_in[0];
    const float* fr_w1   = (const float*)d_in[1];
    const float* fr_b1   = (const float*)d_in[2];
    const float* fr_w2   = (const float*)d_in[3];
    const float* fr_b2   = (const float*)d_in[4];
    const float* tc_w1   = (const float*)d_in[5];
    const float* tc_b1   = (const float*)d_in[6];
    const float* tc_w2   = (const float*)d_in[7];
    const float* tc_b2   = (const float*)d_in[8];
    const float* centers = (const float*)d_in[9];
    const float* fc_w1   = (const float*)d_in[10];
    const float* fc_b1   = (const float*)d_in[11];
    const float* fc_w2   = (const float*)d_in[12];
    const float* fc_b2   = (const float*)d_in[13];
    const float* g_w     = (const float*)d_in[14];
    const float* g_b     = (const float*)d_in[15];
    float* out = (float*)d_out;

#define SYM(p, s) { void* _t; cudaGetSymbolAddress(&_t, s); p = (decltype(p))_t; }
    __nv_bfloat16 *qh, *ql, *h1h, *h1l, *xrh, *xrl, *t1h, *t1l, *wth, *wtl, *hfh, *hfl;
    __nv_bfloat16 *w1th, *w1tl, *w2th, *w2tl, *c1th, *c1tl, *c2th, *c2tl;
    __nv_bfloat16 *f2th, *f2tl, *fcth, *fctl, *gwth, *gwtl;
    float *xrf, *tpf, *gtf;
    SYM(qh, g_qh);   SYM(ql, g_ql);
    SYM(h1h, g_h1h); SYM(h1l, g_h1l);
    SYM(xrh, g_xrh); SYM(xrl, g_xrl);
    SYM(t1h, g_t1h); SYM(t1l, g_t1l);
    SYM(wth, g_wth); SYM(wtl, g_wtl);
    SYM(hfh, g_hfh); SYM(hfl, g_hfl);
    SYM(xrf, g_xrf); SYM(tpf, g_tpf); SYM(gtf, g_gtf);
    SYM(w1th, g_w1th); SYM(w1tl, g_w1tl);
    SYM(w2th, g_w2th); SYM(w2tl, g_w2tl);
    SYM(c1th, g_c1th); SYM(c1tl, g_c1tl);
    SYM(c2th, g_c2th); SYM(c2tl, g_c2tl);
    SYM(f2th, g_f2th); SYM(f2tl, g_f2tl);
    SYM(fcth, g_fcth); SYM(fctl, g_fctl);
    SYM(gwth, g_gwth); SYM(gwtl, g_gwtl);
#undef SYM

    cudaFuncSetAttribute(mm_k<A_ROLL,   EP_GELU_BF>, cudaFuncAttributeMaxDynamicSharedMemorySize, SMEM_DYN);
    cudaFuncSetAttribute(mm_k<A_DIRECT, EP_BF_F32>,  cudaFuncAttributeMaxDynamicSharedMemorySize, SMEM_DYN);
    cudaFuncSetAttribute(mm_k<A_DIRECT, EP_GELU_BF>, cudaFuncAttributeMaxDynamicSharedMemorySize, SMEM_DYN);
    cudaFuncSetAttribute(mm_k<A_DIRECT, EP_F32>,     cudaFuncAttributeMaxDynamicSharedMemorySize, SMEM_DYN);
    cudaFuncSetAttribute(mm_k<A_CONCAT, EP_SIG>,     cudaFuncAttributeMaxDynamicSharedMemorySize, SMEM_DYN);
    cudaFuncSetAttribute(mm_k<A_CONCAT, EP_GELU_BF>, cudaFuncAttributeMaxDynamicSharedMemorySize, SMEM_DYN);
    cudaFuncSetAttribute(mm_k<A_DIRECT, EP_FINAL>,   cudaFuncAttributeMaxDynamicSharedMemorySize, SMEM_DYN);

    // ---- conversions ----
    qconv_k<<<2048, 256>>>(queries, qh, ql, (int)NELE);
    {
        dim3 b(32, 8);
        wconv_k<<<dim3(32, 7168/32), b>>>(fr_w1, w1th, w1tl, 7168, 1024);
        wconv_k<<<dim3(32, 1024/32), b>>>(fr_w2, w2th, w2tl, 1024, 1024);
        wconv_k<<<dim3(32, 1024/32), b>>>(tc_w1, c1th, c1tl, 1024, 1024);
        wconv_k<<<dim3(32, 1024/32), b>>>(tc_w2, c2th, c2tl, 1024, 1024);
        wconv_k<<<dim3(32, 1024/32), b>>>(fc_w2, f2th, f2tl, 1024, 1024);
        wconv_k<<<dim3(32, 2048/32), b>>>(fc_w1, fcth, fctl, 2048, 1024);
        wconv_k<<<dim3(32, 2048/32), b>>>(g_w,   gwth, gwtl, 2048, 1024);
    }

    dim3 grid(8, 128), block(256);

    // 1) h1 = gelu(fusion @ fr_w1 + fr_b1)   K=7168 (roll-gathered)
    mm_k<A_ROLL, EP_GELU_BF><<<grid, block, SMEM_DYN>>>(
        qh, ql, nullptr, nullptr, w1th, w1tl, fr_b1, 7168,
        h1h, h1l, nullptr, nullptr, nullptr);
    // 2) x_ring = h1 @ fr_w2 + fr_b2   (bf16 hi/lo + f32)
    mm_k<A_DIRECT, EP_BF_F32><<<grid, block, SMEM_DYN>>>(
        h1h, h1l, nullptr, nullptr, w2th, w2tl, fr_b2, 1024,
        xrh, xrl, xrf, nullptr, nullptr);
    // 3) t1 = gelu(x_ring @ tc_w1 + tc_b1)
    mm_k<A_DIRECT, EP_GELU_BF><<<grid, block, SMEM_DYN>>>(
        xrh, xrl, nullptr, nullptr, c1th, c1tl, tc_b1, 1024,
        t1h, t1l, nullptr, nullptr, nullptr);
    // 4) token_proj = t1 @ tc_w2 + tc_b2   (f32)
    mm_k<A_DIRECT, EP_F32><<<grid, block, SMEM_DYN>>>(
        t1h, t1l, nullptr, nullptr, c2th, c2tl, tc_b2, 1024,
        nullptr, nullptr, tpf, nullptr, nullptr);
    // 5) weighted = softmax(tp @ centers^T) @ centers  (bf16 hi/lo)
    cluster_k<<<MT / 8, 256>>>(tpf, centers, wth, wtl);
    // 6) gate = sigmoid([xr|wt] @ g_w + g_b)   K=2048 (f32)
    mm_k<A_CONCAT, EP_SIG><<<grid, block, SMEM_DYN>>>(
        xrh, xrl, wth, wtl, gwth, gwtl, g_b, 2048,
        nullptr, nullptr, gtf, nullptr, nullptr);
    // 7) h_fc = gelu([xr|wt] @ fc_w1 + fc_b1)  K=2048
    mm_k<A_CONCAT, EP_GELU_BF><<<grid, block, SMEM_DYN>>>(
        xrh, xrl, wth, wtl, fcth, fctl, fc_b1, 2048,
        hfh, hfl, nullptr, nullptr, nullptr);
    // 8) out = gate * (h_fc @ fc_w2 + fc_b2) + (1-gate) * x_ring
    mm_k<A_DIRECT, EP_FINAL><<<grid, block, SMEM_DYN>>>(
        hfh, hfl, nullptr, nullptr, f2th, f2tl, fc_b2, 1024,
        nullptr, nullptr, out, gtf, xrf);
}

// round 5
// speedup vs baseline: 4.0505x; 1.0504x over previous
#include <cuda_runtime.h>
#include <cuda_bf16.h>
#include <cstdint>
#include <math.h>

// ---------------------------------------------------------------------------
// CenterRingFormerPlus via HMMA (mma.sync bf16, hi/lo split 3-MMA for accuracy)
// 128x128 CTA tile, BK=64 stages, 3-stage cp.async ring (ONE sync per stage),
// double-buffered ldmatrix fragments, SW128 swizzle, fused epilogues.
// Conversions collapsed to 5 launches so ncu -s5 -c1 captures mm1 (K=7168).
// ---------------------------------------------------------------------------

#define MT 16384
#define NT 1024
#define NELE (16384u * 1024u)

// ---- scratch (device globals; no allocation allowed) ----
__device__ __nv_bfloat16 g_qh[NELE],  g_ql[NELE];
__device__ __nv_bfloat16 g_h1h[NELE], g_h1l[NELE];
__device__ __nv_bfloat16 g_xrh[NELE], g_xrl[NELE];
__device__ __nv_bfloat16 g_t1h[NELE], g_t1l[NELE];
__device__ __nv_bfloat16 g_wth[NELE], g_wtl[NELE];
__device__ __nv_bfloat16 g_hfh[NELE], g_hfl[NELE];
__device__ float g_xrf[NELE];
__device__ float g_tpf[NELE];
__device__ float g_gtf[NELE];
// transposed weights, [N=1024, K] K-major, hi/lo bf16
__device__ __nv_bfloat16 g_w1th[1024u*7168u], g_w1tl[1024u*7168u];
__device__ __nv_bfloat16 g_w2th[1024u*1024u], g_w2tl[1024u*1024u];
__device__ __nv_bfloat16 g_c1th[1024u*1024u], g_c1tl[1024u*1024u];
__device__ __nv_bfloat16 g_c2th[1024u*1024u], g_c2tl[1024u*1024u];
__device__ __nv_bfloat16 g_f2th[1024u*1024u], g_f2tl[1024u*1024u];
__device__ __nv_bfloat16 g_fcth[1024u*2048u], g_fctl[1024u*2048u];
__device__ __nv_bfloat16 g_gwth[1024u*2048u], g_gwtl[1024u*2048u];

__constant__ int c_shifts[7] = {1, -1, 0, 2, -2, 4, -4};

enum { A_DIRECT = 0, A_ROLL = 1, A_CONCAT = 2 };
enum { EP_GELU_BF = 0, EP_BF_F32 = 1, EP_F32 = 2, EP_SIG = 3, EP_FINAL = 4 };

// ---------------- helpers ----------------
static __device__ __forceinline__ uint32_t s2u(const void* p) {
    return (uint32_t)__cvta_generic_to_shared(p);
}
static __device__ __forceinline__ void cp16(uint32_t d, const void* s) {
    asm volatile("cp.async.cg.shared.global [%0], [%1], 16;\n" :: "r"(d), "l"(s));
}
static __device__ __forceinline__ void cp_commit() {
    asm volatile("cp.async.commit_group;\n" ::: "memory");
}
static __device__ __forceinline__ void ldm4(uint32_t& r0, uint32_t& r1,
                                            uint32_t& r2, uint32_t& r3, uint32_t a) {
    asm volatile("ldmatrix.sync.aligned.m8n8.x4.shared.b16 {%0,%1,%2,%3}, [%4];"
                 : "=r"(r0), "=r"(r1), "=r"(r2), "=r"(r3) : "r"(a));
}
static __device__ __forceinline__ void mma16816(float* d, const uint32_t* a,
                                                const uint32_t* b) {
    asm volatile(
        "mma.sync.aligned.m16n8k16.row.col.f32.bf16.bf16.f32 "
        "{%0,%1,%2,%3}, {%4,%5,%6,%7}, {%8,%9}, {%0,%1,%2,%3};"
        : "+f"(d[0]), "+f"(d[1]), "+f"(d[2]), "+f"(d[3])
        : "r"(a[0]), "r"(a[1]), "r"(a[2]), "r"(a[3]), "r"(b[0]), "r"(b[1]));
}
static __device__ __forceinline__ float gelu_exact(float x) {
    return 0.5f * x * (1.0f + erff(x * 0.7071067811865476f));
}
static __device__ __forceinline__ void split_bf(float v, __nv_bfloat16& h, __nv_bfloat16& l) {
    h = __float2bfloat16(v);
    l = __float2bfloat16(v - __bfloat162float(h));
}

// ---------------- tile loader (BK=64, SW128 swizzle, hi/lo A and B) --------
#define STG_BYTES 65536
#define T_AH 0
#define T_AL 16384
#define T_BH 32768
#define T_BL 49152

template <int ASRC>
static __device__ __forceinline__ void load_stage(
    uint32_t buf,
    const __nv_bfloat16* __restrict__ Ah, const __nv_bfloat16* __restrict__ Al,
    const __nv_bfloat16* __restrict__ A2h, const __nv_bfloat16* __restrict__ A2l,
    const __nv_bfloat16* __restrict__ Bh, const __nv_bfloat16* __restrict__ Bl,
    int K, int k0, int bm, int bn, int tid)
{
#pragma unroll
    for (int i = 0; i < 4; i++) {
        const int c = tid + i * 256;
        const int r = c >> 3, ch = c & 7;
        const uint32_t bo = (uint32_t)(r * 128 + ch * 16);
        const uint32_t sw = bo ^ ((bo >> 3) & 0x70);

        const __nv_bfloat16 *pah, *pal;
        size_t aoff;
        if (ASRC == A_DIRECT) {
            aoff = (size_t)(bm + r) * (size_t)K + (size_t)(k0 + ch * 8);
            pah = Ah; pal = Al;
        } else if (ASRC == A_ROLL) {
            const int sh = c_shifts[k0 >> 10];
            const int m = bm + r, bb = m >> 11, nn = m & 2047;
            const int src = (nn - sh) & 2047;
            aoff = ((size_t)((bb << 11) | src)) * 1024u + (size_t)((k0 & 1023) + ch * 8);
            pah = Ah; pal = Al;
        } else {
            if (k0 < 1024) { pah = Ah; pal = Al; } else { pah = A2h; pal = A2l; }
            aoff = (size_t)(bm + r) * 1024u + (size_t)((k0 & 1023) + ch * 8);
        }
        cp16(buf + T_AH + sw, pah + aoff);
        cp16(buf + T_AL + sw, pal + aoff);

        const size_t boff = (size_t)(bn + r) * (size_t)K + (size_t)(k0 + ch * 8);
        cp16(buf + T_BH + sw, Bh + boff);
        cp16(buf + T_BL + sw, Bl + boff);
    }
}

// ---------------- per-kk fragment load (12 ldmatrix) ----------------
static __device__ __forceinline__ void ldfrag(
    uint32_t buf, int kk, int wm, int wn,
    int a_row, int a_kb, int b_row, int b_kb,
    uint32_t (*ah)[4], uint32_t (*al)[4], uint32_t (*bh)[2], uint32_t (*bl)[2])
{
#pragma unroll
    for (int p = 0; p < 2; p++) {
        const uint32_t bo = (uint32_t)((wn + p * 16 + b_row) * 128 + kk * 32 + b_kb);
        const uint32_t sw = bo ^ ((bo >> 3) & 0x70);
        ldm4(bh[2*p][0], bh[2*p][1], bh[2*p+1][0], bh[2*p+1][1], buf + T_BH + sw);
        ldm4(bl[2*p][0], bl[2*p][1], bl[2*p+1][0], bl[2*p+1][1], buf + T_BL + sw);
    }
#pragma unroll
    for (int mt = 0; mt < 4; mt++) {
        const uint32_t bo = (uint32_t)((wm + mt * 16 + a_row) * 128 + kk * 32 + a_kb);
        const uint32_t sw = bo ^ ((bo >> 3) & 0x70);
        ldm4(ah[mt][0], ah[mt][1], ah[mt][2], ah[mt][3], buf + T_AH + sw);
        ldm4(al[mt][0], al[mt][1], al[mt][2], al[mt][3], buf + T_AL + sw);
    }
}

// ---------------- main GEMM kernel ----------------
#define SMEM_DYN (1024 + 3 * STG_BYTES)

template <int ASRC, int EPI>
__global__ __launch_bounds__(256, 1)
void mm_k(const __nv_bfloat16* __restrict__ Ah, const __nv_bfloat16* __restrict__ Al,
          const __nv_bfloat16* __restrict__ A2h, const __nv_bfloat16* __restrict__ A2l,
          const __nv_bfloat16* __restrict__ Bth, const __nv_bfloat16* __restrict__ Btl,
          const float* __restrict__ bias, int K,
          __nv_bfloat16* __restrict__ Oh, __nv_bfloat16* __restrict__ Ol,
          float* __restrict__ Of,
          const float* __restrict__ e_gate, const float* __restrict__ e_xr)
{
    extern __shared__ char smraw[];
    const uint32_t bufbase = (s2u(smraw) + 1023u) & ~1023u;
    const int tid = threadIdx.x, wid = tid >> 5, lane = tid & 31;
    const int bn = blockIdx.x * 128, bm = blockIdx.y * 128;

    const int wm = (wid >> 2) * 64;   // warp row offset (0 or 64)
    const int wn = (wid & 3) * 32;    // warp col offset (0,32,64,96)

    float acc[4][4][4];
#pragma unroll
    for (int mt = 0; mt < 4; mt++)
#pragma unroll
        for (int nt = 0; nt < 4; nt++)
#pragma unroll
            for (int r = 0; r < 4; r++) acc[mt][nt][r] = 0.0f;

    const int nst = K >> 6;

    // prologue: stages 0 and 1
    load_stage<ASRC>(bufbase,             Ah, Al, A2h, A2l, Bth, Btl, K, 0,  bm, bn, tid);
    cp_commit();
    load_stage<ASRC>(bufbase + STG_BYTES, Ah, Al, A2h, A2l, Bth, Btl, K, 64, bm, bn, tid);
    cp_commit();

    // per-thread ldmatrix address components
    const int a_row = lane & 15;
    const int a_kb  = ((lane >> 4) & 1) * 16;
    const int b_row = (lane & 7) + ((lane >> 4) & 1) * 8;
    const int b_kb  = ((lane >> 3) & 1) * 16;

    // double-buffered fragments
    uint32_t ah[2][4][4], al[2][4][4], bh[2][4][2], bl[2][4][2];

    for (int s = 0; s < nst; s++) {
        if (s < nst - 1) asm volatile("cp.async.wait_group 1;" ::: "memory");
        else             asm volatile("cp.async.wait_group 0;" ::: "memory");
        __syncthreads();   // data(s) visible AND buffer (s-1)%3 fully consumed

        const uint32_t buf = bufbase + (uint32_t)(s % 3) * STG_BYTES;

        ldfrag(buf, 0, wm, wn, a_row, a_kb, b_row, b_kb, ah[0], al[0], bh[0], bl[0]);
#pragma unroll
        for (int kk = 0; kk < 4; kk++) {
            const int cur = kk & 1, nxt = cur ^ 1;
            if (kk < 3)
                ldfrag(buf, kk + 1, wm, wn, a_row, a_kb, b_row, b_kb,
                       ah[nxt], al[nxt], bh[nxt], bl[nxt]);
#pragma unroll
            for (int mt = 0; mt < 4; mt++)
#pragma unroll
                for (int nt = 0; nt < 4; nt++) {
                    mma16816(acc[mt][nt], ah[cur][mt], bh[cur][nt]);
                    mma16816(acc[mt][nt], ah[cur][mt], bl[cur][nt]);
                    mma16816(acc[mt][nt], al[cur][mt], bh[cur][nt]);
                }
        }

        // issue loads for stage s+2 (overwrites buffer consumed at s-1;
        // protected by the __syncthreads at the top of this iteration)
        if (s + 2 < nst) {
            load_stage<ASRC>(bufbase + (uint32_t)((s + 2) % 3) * STG_BYTES,
                             Ah, Al, A2h, A2l, Bth, Btl, K, (s + 2) * 64, bm, bn, tid);
            cp_commit();
        }
    }

    // ---- epilogue (register accumulators, fused) ----
    const int qr = lane >> 2;
    const int qc = (lane & 3) * 2;
#pragma unroll
    for (int mt = 0; mt < 4; mt++) {
#pragma unroll
        for (int nt = 0; nt < 4; nt++) {
            const int col = bn + wn + nt * 8 + qc;
            const float2 bs = *(const float2*)(bias + col);
#pragma unroll
            for (int h = 0; h < 2; h++) {
                const int row = bm + wm + mt * 16 + qr + h * 8;
                const size_t off = (size_t)row * 1024u + (size_t)col;
                float v0 = acc[mt][nt][2*h]     + bs.x;
                float v1 = acc[mt][nt][2*h + 1] + bs.y;

                if (EPI == EP_GELU_BF) {
                    v0 = gelu_exact(v0);  v1 = gelu_exact(v1);
                    __nv_bfloat162 hh, ll;
                    split_bf(v0, hh.x, ll.x);  split_bf(v1, hh.y, ll.y);
                    *(__nv_bfloat162*)(Oh + off) = hh;
                    *(__nv_bfloat162*)(Ol + off) = ll;
                } else if (EPI == EP_BF_F32) {
                    __nv_bfloat162 hh, ll;
                    split_bf(v0, hh.x, ll.x);  split_bf(v1, hh.y, ll.y);
                    *(__nv_bfloat162*)(Oh + off) = hh;
                    *(__nv_bfloat162*)(Ol + off) = ll;
                    *(float2*)(Of + off) = make_float2(v0, v1);
                } else if (EPI == EP_F32) {
                    *(float2*)(Of + off) = make_float2(v0, v1);
                } else if (EPI == EP_SIG) {
                    v0 = 1.0f / (1.0f + expf(-v0));
                    v1 = 1.0f / (1.0f + expf(-v1));
                    *(float2*)(Of + off) = make_float2(v0, v1);
                } else {  // EP_FINAL
                    const float2 g = *(const float2*)(e_gate + off);
                    const float2 x = *(const float2*)(e_xr + off);
                    *(float2*)(Of + off) = make_float2(
                        g.x * v0 + (1.0f - g.x) * x.x,
                        g.y * v1 + (1.0f - g.y) * x.y);
                }
            }
        }
    }
}

// ---------------- weight transpose-convert: W[K,N] f32 -> Th/Tl[N,K] bf16 ----
static __device__ __forceinline__ void wconv_body(
    const float* __restrict__ W, __nv_bfloat16* __restrict__ Th,
    __nv_bfloat16* __restrict__ Tl, int K, int N, float* t /* [32][33] */)
{
    const int n0 = blockIdx.x * 32, k0 = blockIdx.y * 32;
    const int tx = threadIdx.x, ty = threadIdx.y;
#pragma unroll
    for (int i = 0; i < 4; i++)
        t[(ty + i * 8) * 33 + tx] = W[(size_t)(k0 + ty + i * 8) * N + n0 + tx];
    __syncthreads();
#pragma unroll
    for (int i = 0; i < 4; i++) {
        const float v = t[tx * 33 + ty + i * 8];
        __nv_bfloat16 h, l;
        split_bf(v, h, l);
        const size_t o = (size_t)(n0 + ty + i * 8) * K + k0 + tx;
        Th[o] = h;  Tl[o] = l;
    }
}

__global__ void wconv_k(const float* __restrict__ W, __nv_bfloat16* __restrict__ Th,
                        __nv_bfloat16* __restrict__ Tl, int K, int N)
{
    __shared__ float t[32 * 33];
    wconv_body(W, Th, Tl, K, N, t);
}

// 4 weights in one launch; z selects. z 0,1: K=1024 (skip y>=32); z 2,3: K=2048.
__global__ void wconv4_k(const float* W0, __nv_bfloat16* T0h, __nv_bfloat16* T0l,
                         const float* W1, __nv_bfloat16* T1h, __nv_bfloat16* T1l,
                         const float* W2, __nv_bfloat16* T2h, __nv_bfloat16* T2l,
                         const float* W3, __nv_bfloat16* T3h, __nv_bfloat16* T3l)
{
    __shared__ float t[32 * 33];
    const int z = blockIdx.z;
    if (z == 0) { if (blockIdx.y >= 32) return; wconv_body(W0, T0h, T0l, 1024, 1024, t); }
    else if (z == 1) { if (blockIdx.y >= 32) return; wconv_body(W1, T1h, T1l, 1024, 1024, t); }
    else if (z == 2) { wconv_body(W2, T2h, T2l, 2048, 1024, t); }
    else { wconv_body(W3, T3h, T3l, 2048, 1024, t); }
}

// ---------------- queries convert ----------------
__global__ void qconv_k(const float* __restrict__ Q, __nv_bfloat16* __restrict__ Hh,
                        __nv_bfloat16* __restrict__ Hl, int n)
{
    for (int i = blockIdx.x * 256 + threadIdx.x; i < n; i += gridDim.x * 256) {
        __nv_bfloat16 h, l;
        split_bf(Q[i], h, l);
        Hh[i] = h;  Hl[i] = l;
    }
}

// ---------------- cluster softmax ----------------
__global__ __launch_bounds__(256)
void cluster_k(const float* __restrict__ tproj, const float* __restrict__ centers,
               __nv_bfloat16* __restrict__ wh, __nv_bfloat16* __restrict__ wl)
{
    __shared__ float sc[4 * 1024];
    const int tid = threadIdx.x;
    for (int i = tid * 4; i < 4096; i += 256 * 4)
        *(float4*)&sc[i] = *(const float4*)&centers[i];
    __syncthreads();

    const int warp = tid >> 5, lane = tid & 31;
    const size_t row = (size_t)blockIdx.x * 8 + warp;
    const float* tp = tproj + row * 1024u;

    float d0 = 0.f, d1 = 0.f, d2 = 0.f, d3 = 0.f;
    for (int d = lane * 4; d < 1024; d += 128) {
        float4 t  = *(const float4*)(tp + d);
        float4 c0 = *(const float4*)(sc + d);
        float4 c1 = *(const float4*)(sc + 1024 + d);
        float4 c2 = *(const float4*)(sc + 2048 + d);
        float4 c3 = *(const float4*)(sc + 3072 + d);
        d0 += t.x*c0.x + t.y*c0.y + t.z*c0.z + t.w*c0.w;
        d1 += t.x*c1.x + t.y*c1.y + t.z*c1.z + t.w*c1.w;
        d2 += t.x*c2.x + t.y*c2.y + t.z*c2.z + t.w*c2.w;
        d3 += t.x*c3.x + t.y*c3.y + t.z*c3.z + t.w*c3.w;
    }
#pragma unroll
    for (int off = 16; off > 0; off >>= 1) {
        d0 += __shfl_xor_sync(0xffffffffu, d0, off);
        d1 += __shfl_xor_sync(0xffffffffu, d1, off);
        d2 += __shfl_xor_sync(0xffffffffu, d2, off);
        d3 += __shfl_xor_sync(0xffffffffu, d3, off);
    }
    const float mx = fmaxf(fmaxf(d0, d1), fmaxf(d2, d3));
    const float e0 = expf(d0 - mx), e1 = expf(d1 - mx),
                e2 = expf(d2 - mx), e3 = expf(d3 - mx);
    const float inv = 1.0f / (e0 + e1 + e2 + e3);
    const float w0 = e0*inv, w1 = e1*inv, w2 = e2*inv, w3 = e3*inv;

    for (int d = lane * 4; d < 1024; d += 128) {
        float4 c0 = *(const float4*)(sc + d);
        float4 c1 = *(const float4*)(sc + 1024 + d);
        float4 c2 = *(const float4*)(sc + 2048 + d);
        float4 c3 = *(const float4*)(sc + 3072 + d);
        float o[4];
        o[0] = w0*c0.x + w1*c1.x + w2*c2.x + w3*c3.x;
        o[1] = w0*c0.y + w1*c1.y + w2*c2.y + w3*c3.y;
        o[2] = w0*c0.z + w1*c1.z + w2*c2.z + w3*c3.z;
        o[3] = w0*c0.w + w1*c1.w + w2*c2.w + w3*c3.w;
        __nv_bfloat162 h2[2], l2[2];
#pragma unroll
        for (int p = 0; p < 2; p++) {
            split_bf(o[2*p],   h2[p].x, l2[p].x);
            split_bf(o[2*p+1], h2[p].y, l2[p].y);
        }
        *(uint2*)(wh + row * 1024u + d) = *(uint2*)h2;
        *(uint2*)(wl + row * 1024u + d) = *(uint2*)l2;
    }
}

// ---------------- launch ----------------
extern "C" void kernel_launch(void* const* d_in, const int* in_sizes, int n_in,
                              void* d_out, int out_size)
{
    const float* queries = (const float*)d_in[0];
    const float* fr_w1   = (const float*)d_in[1];
    const float* fr_b1   = (const float*)d_in[2];
    const float* fr_w2   = (const float*)d_in[3];
    const float* fr_b2   = (const float*)d_in[4];
    const float* tc_w1   = (const float*)d_in[5];
    const float* tc_b1   = (const float*)d_in[6];
    const float* tc_w2   = (const float*)d_in[7];
    const float* tc_b2   = (const float*)d_in[8];
    const float* centers = (const float*)d_in[9];
    const float* fc_w1   = (const float*)d_in[10];
    const float* fc_b1   = (const float*)d_in[11];
    const float* fc_w2   = (const float*)d_in[12];
    const float* fc_b2   = (const float*)d_in[13];
    const float* g_w     = (const float*)d_in[14];
    const float* g_b     = (const float*)d_in[15];
    float* out = (float*)d_out;

#define SYM(p, s) { void* _t; cudaGetSymbolAddress(&_t, s); p = (decltype(p))_t; }
    __nv_bfloat16 *qh, *ql, *h1h, *h1l, *xrh, *xrl, *t1h, *t1l, *wth, *wtl, *hfh, *hfl;
    __nv_bfloat16 *w1th, *w1tl, *w2th, *w2tl, *c1th, *c1tl, *c2th, *c2tl;
    __nv_bfloat16 *f2th, *f2tl, *fcth, *fctl, *gwth, *gwtl;
    float *xrf, *tpf, *gtf;
    SYM(qh, g_qh);   SYM(ql, g_ql);
    SYM(h1h, g_h1h); SYM(h1l, g_h1l);
    SYM(xrh, g_xrh); SYM(xrl, g_xrl);
    SYM(t1h, g_t1h); SYM(t1l, g_t1l);
    SYM(wth, g_wth); SYM(wtl, g_wtl);
    SYM(hfh, g_hfh); SYM(hfl, g_hfl);
    SYM(xrf, g_xrf); SYM(tpf, g_tpf); SYM(gtf, g_gtf);
    SYM(w1th, g_w1th); SYM(w1tl, g_w1tl);
    SYM(w2th, g_w2th); SYM(w2tl, g_w2tl);
    SYM(c1th, g_c1th); SYM(c1tl, g_c1tl);
    SYM(c2th, g_c2th); SYM(c2tl, g_c2tl);
    SYM(f2th, g_f2th); SYM(f2tl, g_f2tl);
    SYM(fcth, g_fcth); SYM(fctl, g_fctl);
    SYM(gwth, g_gwth); SYM(gwtl, g_gwtl);
#undef SYM

    cudaFuncSetAttribute(mm_k<A_ROLL,   EP_GELU_BF>, cudaFuncAttributeMaxDynamicSharedMemorySize, SMEM_DYN);
    cudaFuncSetAttribute(mm_k<A_DIRECT, EP_BF_F32>,  cudaFuncAttributeMaxDynamicSharedMemorySize, SMEM_DYN);
    cudaFuncSetAttribute(mm_k<A_DIRECT, EP_GELU_BF>, cudaFuncAttributeMaxDynamicSharedMemorySize, SMEM_DYN);
    cudaFuncSetAttribute(mm_k<A_DIRECT, EP_F32>,     cudaFuncAttributeMaxDynamicSharedMemorySize, SMEM_DYN);
    cudaFuncSetAttribute(mm_k<A_CONCAT, EP_SIG>,     cudaFuncAttributeMaxDynamicSharedMemorySize, SMEM_DYN);
    cudaFuncSetAttribute(mm_k<A_CONCAT, EP_GELU_BF>, cudaFuncAttributeMaxDynamicSharedMemorySize, SMEM_DYN);
    cudaFuncSetAttribute(mm_k<A_DIRECT, EP_FINAL>,   cudaFuncAttributeMaxDynamicSharedMemorySize, SMEM_DYN);

    dim3 wcb(32, 8);

    // ---- exactly 5 conversion launches (so launch #6 = mm1 for ncu -s5 -c1) ----
    qconv_k<<<2048, 256>>>(queries, qh, ql, (int)NELE);                       // 1
    wconv_k<<<dim3(32, 7168/32), wcb>>>(fr_w1, w1th, w1tl, 7168, 1024);       // 2
    wconv_k<<<dim3(32, 1024/32), wcb>>>(fr_w2, w2th, w2tl, 1024, 1024);       // 3
    wconv_k<<<dim3(32, 1024/32), wcb>>>(tc_w1, c1th, c1tl, 1024, 1024);       // 4
    wconv4_k<<<dim3(32, 64, 4), wcb>>>(tc_w2, c2th, c2tl, fc_w2, f2th, f2tl,  // 5
                                       fc_w1, fcth, fctl, g_w, gwth, gwtl);

    dim3 grid(8, 128), block(256);

    // 6) h1 = gelu(fusion @ fr_w1 + fr_b1)   K=7168 (roll-gathered) — ncu target
    mm_k<A_ROLL, EP_GELU_BF><<<grid, block, SMEM_DYN>>>(
        qh, ql, nullptr, nullptr, w1th, w1tl, fr_b1, 7168,
        h1h, h1l, nullptr, nullptr, nullptr);
    // x_ring = h1 @ fr_w2 + fr_b2
    mm_k<A_DIRECT, EP_BF_F32><<<grid, block, SMEM_DYN>>>(
        h1h, h1l, nullptr, nullptr, w2th, w2tl, fr_b2, 1024,
        xrh, xrl, xrf, nullptr, nullptr);
    // t1 = gelu(x_ring @ tc_w1 + tc_b1)
    mm_k<A_DIRECT, EP_GELU_BF><<<grid, block, SMEM_DYN>>>(
        xrh, xrl, nullptr, nullptr, c1th, c1tl, tc_b1, 1024,
        t1h, t1l, nullptr, nullptr, nullptr);
    // token_proj = t1 @ tc_w2 + tc_b2
    mm_k<A_DIRECT, EP_F32><<<grid, block, SMEM_DYN>>>(
        t1h, t1l, nullptr, nullptr, c2th, c2tl, tc_b2, 1024,
        nullptr, nullptr, tpf, nullptr, nullptr);
    // weighted = softmax(tp @ centers^T) @ centers
    cluster_k<<<MT / 8, 256>>>(tpf, centers, wth, wtl);
    // gate = sigmoid([xr|wt] @ g_w + g_b)
    mm_k<A_CONCAT, EP_SIG><<<grid, block, SMEM_DYN>>>(
        xrh, xrl, wth, wtl, gwth, gwtl, g_b, 2048,
        nullptr, nullptr, gtf, nullptr, nullptr);
    // h_fc = gelu([xr|wt] @ fc_w1 + fc_b1)
    mm_k<A_CONCAT, EP_GELU_BF><<<grid, block, SMEM_DYN>>>(
        xrh, xrl, wth, wtl, fcth, fctl, fc_b1, 2048,
        hfh, hfl, nullptr, nullptr, nullptr);
    // out = gate * (h_fc @ fc_w2 + fc_b2) + (1-gate) * x_ring
    mm_k<A_DIRECT, EP_FINAL><<<grid, block, SMEM_DYN>>>(
        hfh, hfl, nullptr, nullptr, f2th, f2tl, fc_b2, 1024,
        nullptr, nullptr, out, gtf, xrf);
}

// round 6
// speedup vs baseline: 4.0529x; 1.0006x over previous
#include <cuda_runtime.h>
#include <cuda_bf16.h>
#include <cstdint>
#include <math.h>

// ---------------------------------------------------------------------------
// CenterRingFormerPlus via HMMA (mma.sync bf16, hi/lo split 3-MMA for accuracy)
// 128x128 CTA tile, BK=64 stages, 3-stage cp.async ring (ONE sync per stage),
// double-buffered ldmatrix fragments, TERM-MAJOR MMA order (same-acc reuse
// distance 16 instead of 1), SW128 swizzle, fused epilogues.
// ---------------------------------------------------------------------------

#define MT 16384
#define NT 1024
#define NELE (16384u * 1024u)

// ---- scratch (device globals; no allocation allowed) ----
__device__ __nv_bfloat16 g_qh[NELE],  g_ql[NELE];
__device__ __nv_bfloat16 g_h1h[NELE], g_h1l[NELE];
__device__ __nv_bfloat16 g_xrh[NELE], g_xrl[NELE];
__device__ __nv_bfloat16 g_t1h[NELE], g_t1l[NELE];
__device__ __nv_bfloat16 g_wth[NELE], g_wtl[NELE];
__device__ __nv_bfloat16 g_hfh[NELE], g_hfl[NELE];
__device__ float g_xrf[NELE];
__device__ float g_tpf[NELE];
__device__ float g_gtf[NELE];
// transposed weights, [N=1024, K] K-major, hi/lo bf16
__device__ __nv_bfloat16 g_w1th[1024u*7168u], g_w1tl[1024u*7168u];
__device__ __nv_bfloat16 g_w2th[1024u*1024u], g_w2tl[1024u*1024u];
__device__ __nv_bfloat16 g_c1th[1024u*1024u], g_c1tl[1024u*1024u];
__device__ __nv_bfloat16 g_c2th[1024u*1024u], g_c2tl[1024u*1024u];
__device__ __nv_bfloat16 g_f2th[1024u*1024u], g_f2tl[1024u*1024u];
__device__ __nv_bfloat16 g_fcth[1024u*2048u], g_fctl[1024u*2048u];
__device__ __nv_bfloat16 g_gwth[1024u*2048u], g_gwtl[1024u*2048u];

__constant__ int c_shifts[7] = {1, -1, 0, 2, -2, 4, -4};

enum { A_DIRECT = 0, A_ROLL = 1, A_CONCAT = 2 };
enum { EP_GELU_BF = 0, EP_BF_F32 = 1, EP_F32 = 2, EP_SIG = 3, EP_FINAL = 4 };

// ---------------- helpers ----------------
static __device__ __forceinline__ uint32_t s2u(const void* p) {
    return (uint32_t)__cvta_generic_to_shared(p);
}
static __device__ __forceinline__ void cp16(uint32_t d, const void* s) {
    asm volatile("cp.async.cg.shared.global [%0], [%1], 16;\n" :: "r"(d), "l"(s));
}
static __device__ __forceinline__ void cp_commit() {
    asm volatile("cp.async.commit_group;\n" ::: "memory");
}
static __device__ __forceinline__ void ldm4(uint32_t& r0, uint32_t& r1,
                                            uint32_t& r2, uint32_t& r3, uint32_t a) {
    asm volatile("ldmatrix.sync.aligned.m8n8.x4.shared.b16 {%0,%1,%2,%3}, [%4];"
                 : "=r"(r0), "=r"(r1), "=r"(r2), "=r"(r3) : "r"(a));
}
static __device__ __forceinline__ void mma16816(float* d, const uint32_t* a,
                                                const uint32_t* b) {
    asm volatile(
        "mma.sync.aligned.m16n8k16.row.col.f32.bf16.bf16.f32 "
        "{%0,%1,%2,%3}, {%4,%5,%6,%7}, {%8,%9}, {%0,%1,%2,%3};"
        : "+f"(d[0]), "+f"(d[1]), "+f"(d[2]), "+f"(d[3])
        : "r"(a[0]), "r"(a[1]), "r"(a[2]), "r"(a[3]), "r"(b[0]), "r"(b[1]));
}
static __device__ __forceinline__ float gelu_exact(float x) {
    return 0.5f * x * (1.0f + erff(x * 0.7071067811865476f));
}
static __device__ __forceinline__ void split_bf(float v, __nv_bfloat16& h, __nv_bfloat16& l) {
    h = __float2bfloat16(v);
    l = __float2bfloat16(v - __bfloat162float(h));
}

// ---------------- tile loader (BK=64, SW128 swizzle, hi/lo A and B) --------
#define STG_BYTES 65536
#define T_AH 0
#define T_AL 16384
#define T_BH 32768
#define T_BL 49152

template <int ASRC>
static __device__ __forceinline__ void load_stage(
    uint32_t buf,
    const __nv_bfloat16* __restrict__ Ah, const __nv_bfloat16* __restrict__ Al,
    const __nv_bfloat16* __restrict__ A2h, const __nv_bfloat16* __restrict__ A2l,
    const __nv_bfloat16* __restrict__ Bh, const __nv_bfloat16* __restrict__ Bl,
    int K, int k0, int bm, int bn, int tid)
{
#pragma unroll
    for (int i = 0; i < 4; i++) {
        const int c = tid + i * 256;
        const int r = c >> 3, ch = c & 7;
        const uint32_t bo = (uint32_t)(r * 128 + ch * 16);
        const uint32_t sw = bo ^ ((bo >> 3) & 0x70);

        const __nv_bfloat16 *pah, *pal;
        size_t aoff;
        if (ASRC == A_DIRECT) {
            aoff = (size_t)(bm + r) * (size_t)K + (size_t)(k0 + ch * 8);
            pah = Ah; pal = Al;
        } else if (ASRC == A_ROLL) {
            const int sh = c_shifts[k0 >> 10];
            const int m = bm + r, bb = m >> 11, nn = m & 2047;
            const int src = (nn - sh) & 2047;
            aoff = ((size_t)((bb << 11) | src)) * 1024u + (size_t)((k0 & 1023) + ch * 8);
            pah = Ah; pal = Al;
        } else {
            if (k0 < 1024) { pah = Ah; pal = Al; } else { pah = A2h; pal = A2l; }
            aoff = (size_t)(bm + r) * 1024u + (size_t)((k0 & 1023) + ch * 8);
        }
        cp16(buf + T_AH + sw, pah + aoff);
        cp16(buf + T_AL + sw, pal + aoff);

        const size_t boff = (size_t)(bn + r) * (size_t)K + (size_t)(k0 + ch * 8);
        cp16(buf + T_BH + sw, Bh + boff);
        cp16(buf + T_BL + sw, Bl + boff);
    }
}

// ---------------- per-kk fragment load (12 ldmatrix) ----------------
static __device__ __forceinline__ void ldfrag(
    uint32_t buf, int kk, int wm, int wn,
    int a_row, int a_kb, int b_row, int b_kb,
    uint32_t (*ah)[4], uint32_t (*al)[4], uint32_t (*bh)[2], uint32_t (*bl)[2])
{
#pragma unroll
    for (int p = 0; p < 2; p++) {
        const uint32_t bo = (uint32_t)((wn + p * 16 + b_row) * 128 + kk * 32 + b_kb);
        const uint32_t sw = bo ^ ((bo >> 3) & 0x70);
        ldm4(bh[2*p][0], bh[2*p][1], bh[2*p+1][0], bh[2*p+1][1], buf + T_BH + sw);
        ldm4(bl[2*p][0], bl[2*p][1], bl[2*p+1][0], bl[2*p+1][1], buf + T_BL + sw);
    }
#pragma unroll
    for (int mt = 0; mt < 4; mt++) {
        const uint32_t bo = (uint32_t)((wm + mt * 16 + a_row) * 128 + kk * 32 + a_kb);
        const uint32_t sw = bo ^ ((bo >> 3) & 0x70);
        ldm4(ah[mt][0], ah[mt][1], ah[mt][2], ah[mt][3], buf + T_AH + sw);
        ldm4(al[mt][0], al[mt][1], al[mt][2], al[mt][3], buf + T_AL + sw);
    }
}

// ---------------- main GEMM kernel ----------------
#define SMEM_DYN (1024 + 3 * STG_BYTES)

template <int ASRC, int EPI>
__global__ __launch_bounds__(256, 1)
void mm_k(const __nv_bfloat16* __restrict__ Ah, const __nv_bfloat16* __restrict__ Al,
          const __nv_bfloat16* __restrict__ A2h, const __nv_bfloat16* __restrict__ A2l,
          const __nv_bfloat16* __restrict__ Bth, const __nv_bfloat16* __restrict__ Btl,
          const float* __restrict__ bias, int K,
          __nv_bfloat16* __restrict__ Oh, __nv_bfloat16* __restrict__ Ol,
          float* __restrict__ Of,
          const float* __restrict__ e_gate, const float* __restrict__ e_xr)
{
    extern __shared__ char smraw[];
    const uint32_t bufbase = (s2u(smraw) + 1023u) & ~1023u;
    const int tid = threadIdx.x, wid = tid >> 5, lane = tid & 31;
    const int bn = blockIdx.x * 128, bm = blockIdx.y * 128;

    const int wm = (wid >> 2) * 64;   // warp row offset (0 or 64)
    const int wn = (wid & 3) * 32;    // warp col offset (0,32,64,96)

    float acc[4][4][4];
#pragma unroll
    for (int mt = 0; mt < 4; mt++)
#pragma unroll
        for (int nt = 0; nt < 4; nt++)
#pragma unroll
            for (int r = 0; r < 4; r++) acc[mt][nt][r] = 0.0f;

    const int nst = K >> 6;

    // prologue: stages 0 and 1
    load_stage<ASRC>(bufbase,             Ah, Al, A2h, A2l, Bth, Btl, K, 0,  bm, bn, tid);
    cp_commit();
    load_stage<ASRC>(bufbase + STG_BYTES, Ah, Al, A2h, A2l, Bth, Btl, K, 64, bm, bn, tid);
    cp_commit();

    // per-thread ldmatrix address components
    const int a_row = lane & 15;
    const int a_kb  = ((lane >> 4) & 1) * 16;
    const int b_row = (lane & 7) + ((lane >> 4) & 1) * 8;
    const int b_kb  = ((lane >> 3) & 1) * 16;

    // double-buffered fragments
    uint32_t ah[2][4][4], al[2][4][4], bh[2][4][2], bl[2][4][2];

    for (int s = 0; s < nst; s++) {
        if (s < nst - 1) asm volatile("cp.async.wait_group 1;" ::: "memory");
        else             asm volatile("cp.async.wait_group 0;" ::: "memory");
        __syncthreads();   // data(s) visible AND buffer (s-1)%3 fully consumed

        const uint32_t buf = bufbase + (uint32_t)(s % 3) * STG_BYTES;

        ldfrag(buf, 0, wm, wn, a_row, a_kb, b_row, b_kb, ah[0], al[0], bh[0], bl[0]);
#pragma unroll
        for (int kk = 0; kk < 4; kk++) {
            const int cur = kk & 1, nxt = cur ^ 1;

            // term 0: ah·bh over all 16 accumulators (reuse distance 16)
#pragma unroll
            for (int mt = 0; mt < 4; mt++)
#pragma unroll
                for (int nt = 0; nt < 4; nt++)
                    mma16816(acc[mt][nt], ah[cur][mt], bh[cur][nt]);

            // prefetch next kk's fragments now — latency hidden under terms 1-2
            if (kk < 3)
                ldfrag(buf, kk + 1, wm, wn, a_row, a_kb, b_row, b_kb,
                       ah[nxt], al[nxt], bh[nxt], bl[nxt]);

            // term 1: ah·bl
#pragma unroll
            for (int mt = 0; mt < 4; mt++)
#pragma unroll
                for (int nt = 0; nt < 4; nt++)
                    mma16816(acc[mt][nt], ah[cur][mt], bl[cur][nt]);

            // term 2: al·bh
#pragma unroll
            for (int mt = 0; mt < 4; mt++)
#pragma unroll
                for (int nt = 0; nt < 4; nt++)
                    mma16816(acc[mt][nt], al[cur][mt], bh[cur][nt]);
        }

        // issue loads for stage s+2 (buffer consumed at s-1; protected by the
        // __syncthreads at the top of the next iteration)
        if (s + 2 < nst) {
            load_stage<ASRC>(bufbase + (uint32_t)((s + 2) % 3) * STG_BYTES,
                             Ah, Al, A2h, A2l, Bth, Btl, K, (s + 2) * 64, bm, bn, tid);
            cp_commit();
        }
    }

    // ---- epilogue (register accumulators, fused) ----
    const int qr = lane >> 2;
    const int qc = (lane & 3) * 2;
#pragma unroll
    for (int mt = 0; mt < 4; mt++) {
#pragma unroll
        for (int nt = 0; nt < 4; nt++) {
            const int col = bn + wn + nt * 8 + qc;
            const float2 bs = *(const float2*)(bias + col);
#pragma unroll
            for (int h = 0; h < 2; h++) {
                const int row = bm + wm + mt * 16 + qr + h * 8;
                const size_t off = (size_t)row * 1024u + (size_t)col;
                float v0 = acc[mt][nt][2*h]     + bs.x;
                float v1 = acc[mt][nt][2*h + 1] + bs.y;

                if (EPI == EP_GELU_BF) {
                    v0 = gelu_exact(v0);  v1 = gelu_exact(v1);
                    __nv_bfloat162 hh, ll;
                    split_bf(v0, hh.x, ll.x);  split_bf(v1, hh.y, ll.y);
                    *(__nv_bfloat162*)(Oh + off) = hh;
                    *(__nv_bfloat162*)(Ol + off) = ll;
                } else if (EPI == EP_BF_F32) {
                    __nv_bfloat162 hh, ll;
                    split_bf(v0, hh.x, ll.x);  split_bf(v1, hh.y, ll.y);
                    *(__nv_bfloat162*)(Oh + off) = hh;
                    *(__nv_bfloat162*)(Ol + off) = ll;
                    *(float2*)(Of + off) = make_float2(v0, v1);
                } else if (EPI == EP_F32) {
                    *(float2*)(Of + off) = make_float2(v0, v1);
                } else if (EPI == EP_SIG) {
                    v0 = 1.0f / (1.0f + expf(-v0));
                    v1 = 1.0f / (1.0f + expf(-v1));
                    *(float2*)(Of + off) = make_float2(v0, v1);
                } else {  // EP_FINAL
                    const float2 g = *(const float2*)(e_gate + off);
                    const float2 x = *(const float2*)(e_xr + off);
                    *(float2*)(Of + off) = make_float2(
                        g.x * v0 + (1.0f - g.x) * x.x,
                        g.y * v1 + (1.0f - g.y) * x.y);
                }
            }
        }
    }
}

// ---------------- weight transpose-convert: W[K,N] f32 -> Th/Tl[N,K] bf16 ----
static __device__ __forceinline__ void wconv_body(
    const float* __restrict__ W, __nv_bfloat16* __restrict__ Th,
    __nv_bfloat16* __restrict__ Tl, int K, int N, float* t /* [32][33] */)
{
    const int n0 = blockIdx.x * 32, k0 = blockIdx.y * 32;
    const int tx = threadIdx.x, ty = threadIdx.y;
#pragma unroll
    for (int i = 0; i < 4; i++)
        t[(ty + i * 8) * 33 + tx] = W[(size_t)(k0 + ty + i * 8) * N + n0 + tx];
    __syncthreads();
#pragma unroll
    for (int i = 0; i < 4; i++) {
        const float v = t[tx * 33 + ty + i * 8];
        __nv_bfloat16 h, l;
        split_bf(v, h, l);
        const size_t o = (size_t)(n0 + ty + i * 8) * K + k0 + tx;
        Th[o] = h;  Tl[o] = l;
    }
}

__global__ void wconv_k(const float* __restrict__ W, __nv_bfloat16* __restrict__ Th,
                        __nv_bfloat16* __restrict__ Tl, int K, int N)
{
    __shared__ float t[32 * 33];
    wconv_body(W, Th, Tl, K, N, t);
}

// 4 weights in one launch; z selects. z 0,1: K=1024 (skip y>=32); z 2,3: K=2048.
__global__ void wconv4_k(const float* W0, __nv_bfloat16* T0h, __nv_bfloat16* T0l,
                         const float* W1, __nv_bfloat16* T1h, __nv_bfloat16* T1l,
                         const float* W2, __nv_bfloat16* T2h, __nv_bfloat16* T2l,
                         const float* W3, __nv_bfloat16* T3h, __nv_bfloat16* T3l)
{
    __shared__ float t[32 * 33];
    const int z = blockIdx.z;
    if (z == 0) { if (blockIdx.y >= 32) return; wconv_body(W0, T0h, T0l, 1024, 1024, t); }
    else if (z == 1) { if (blockIdx.y >= 32) return; wconv_body(W1, T1h, T1l, 1024, 1024, t); }
    else if (z == 2) { wconv_body(W2, T2h, T2l, 2048, 1024, t); }
    else { wconv_body(W3, T3h, T3l, 2048, 1024, t); }
}

// ---------------- queries convert ----------------
__global__ void qconv_k(const float* __restrict__ Q, __nv_bfloat16* __restrict__ Hh,
                        __nv_bfloat16* __restrict__ Hl, int n)
{
    for (int i = blockIdx.x * 256 + threadIdx.x; i < n; i += gridDim.x * 256) {
        __nv_bfloat16 h, l;
        split_bf(Q[i], h, l);
        Hh[i] = h;  Hl[i] = l;
    }
}

// ---------------- cluster softmax ----------------
__global__ __launch_bounds__(256)
void cluster_k(const float* __restrict__ tproj, const float* __restrict__ centers,
               __nv_bfloat16* __restrict__ wh, __nv_bfloat16* __restrict__ wl)
{
    __shared__ float sc[4 * 1024];
    const int tid = threadIdx.x;
    for (int i = tid * 4; i < 4096; i += 256 * 4)
        *(float4*)&sc[i] = *(const float4*)&centers[i];
    __syncthreads();

    const int warp = tid >> 5, lane = tid & 31;
    const size_t row = (size_t)blockIdx.x * 8 + warp;
    const float* tp = tproj + row * 1024u;

    float d0 = 0.f, d1 = 0.f, d2 = 0.f, d3 = 0.f;
    for (int d = lane * 4; d < 1024; d += 128) {
        float4 t  = *(const float4*)(tp + d);
        float4 c0 = *(const float4*)(sc + d);
        float4 c1 = *(const float4*)(sc + 1024 + d);
        float4 c2 = *(const float4*)(sc + 2048 + d);
        float4 c3 = *(const float4*)(sc + 3072 + d);
        d0 += t.x*c0.x + t.y*c0.y + t.z*c0.z + t.w*c0.w;
        d1 += t.x*c1.x + t.y*c1.y + t.z*c1.z + t.w*c1.w;
        d2 += t.x*c2.x + t.y*c2.y + t.z*c2.z + t.w*c2.w;
        d3 += t.x*c3.x + t.y*c3.y + t.z*c3.z + t.w*c3.w;
    }
#pragma unroll
    for (int off = 16; off > 0; off >>= 1) {
        d0 += __shfl_xor_sync(0xffffffffu, d0, off);
        d1 += __shfl_xor_sync(0xffffffffu, d1, off);
        d2 += __shfl_xor_sync(0xffffffffu, d2, off);
        d3 += __shfl_xor_sync(0xffffffffu, d3, off);
    }
    const float mx = fmaxf(fmaxf(d0, d1), fmaxf(d2, d3));
    const float e0 = expf(d0 - mx), e1 = expf(d1 - mx),
                e2 = expf(d2 - mx), e3 = expf(d3 - mx);
    const float inv = 1.0f / (e0 + e1 + e2 + e3);
    const float w0 = e0*inv, w1 = e1*inv, w2 = e2*inv, w3 = e3*inv;

    for (int d = lane * 4; d < 1024; d += 128) {
        float4 c0 = *(const float4*)(sc + d);
        float4 c1 = *(const float4*)(sc + 1024 + d);
        float4 c2 = *(const float4*)(sc + 2048 + d);
        float4 c3 = *(const float4*)(sc + 3072 + d);
        float o[4];
        o[0] = w0*c0.x + w1*c1.x + w2*c2.x + w3*c3.x;
        o[1] = w0*c0.y + w1*c1.y + w2*c2.y + w3*c3.y;
        o[2] = w0*c0.z + w1*c1.z + w2*c2.z + w3*c3.z;
        o[3] = w0*c0.w + w1*c1.w + w2*c2.w + w3*c3.w;
        __nv_bfloat162 h2[2], l2[2];
#pragma unroll
        for (int p = 0; p < 2; p++) {
            split_bf(o[2*p],   h2[p].x, l2[p].x);
            split_bf(o[2*p+1], h2[p].y, l2[p].y);
        }
        *(uint2*)(wh + row * 1024u + d) = *(uint2*)h2;
        *(uint2*)(wl + row * 1024u + d) = *(uint2*)l2;
    }
}

// ---------------- launch ----------------
extern "C" void kernel_launch(void* const* d_in, const int* in_sizes, int n_in,
                              void* d_out, int out_size)
{
    const float* queries = (const float*)d_in[0];
    const float* fr_w1   = (const float*)d_in[1];
    const float* fr_b1   = (const float*)d_in[2];
    const float* fr_w2   = (const float*)d_in[3];
    const float* fr_b2   = (const float*)d_in[4];
    const float* tc_w1   = (const float*)d_in[5];
    const float* tc_b1   = (const float*)d_in[6];
    const float* tc_w2   = (const float*)d_in[7];
    const float* tc_b2   = (const float*)d_in[8];
    const float* centers = (const float*)d_in[9];
    const float* fc_w1   = (const float*)d_in[10];
    const float* fc_b1   = (const float*)d_in[11];
    const float* fc_w2   = (const float*)d_in[12];
    const float* fc_b2   = (const float*)d_in[13];
    const float* g_w     = (const float*)d_in[14];
    const float* g_b     = (const float*)d_in[15];
    float* out = (float*)d_out;

#define SYM(p, s) { void* _t; cudaGetSymbolAddress(&_t, s); p = (decltype(p))_t; }
    __nv_bfloat16 *qh, *ql, *h1h, *h1l, *xrh, *xrl, *t1h, *t1l, *wth, *wtl, *hfh, *hfl;
    __nv_bfloat16 *w1th, *w1tl, *w2th, *w2tl, *c1th, *c1tl, *c2th, *c2tl;
    __nv_bfloat16 *f2th, *f2tl, *fcth, *fctl, *gwth, *gwtl;
    float *xrf, *tpf, *gtf;
    SYM(qh, g_qh);   SYM(ql, g_ql);
    SYM(h1h, g_h1h); SYM(h1l, g_h1l);
    SYM(xrh, g_xrh); SYM(xrl, g_xrl);
    SYM(t1h, g_t1h); SYM(t1l, g_t1l);
    SYM(wth, g_wth); SYM(wtl, g_wtl);
    SYM(hfh, g_hfh); SYM(hfl, g_hfl);
    SYM(xrf, g_xrf); SYM(tpf, g_tpf); SYM(gtf, g_gtf);
    SYM(w1th, g_w1th); SYM(w1tl, g_w1tl);
    SYM(w2th, g_w2th); SYM(w2tl, g_w2tl);
    SYM(c1th, g_c1th); SYM(c1tl, g_c1tl);
    SYM(c2th, g_c2th); SYM(c2tl, g_c2tl);
    SYM(f2th, g_f2th); SYM(f2tl, g_f2tl);
    SYM(fcth, g_fcth); SYM(fctl, g_fctl);
    SYM(gwth, g_gwth); SYM(gwtl, g_gwtl);
#undef SYM

    cudaFuncSetAttribute(mm_k<A_ROLL,   EP_GELU_BF>, cudaFuncAttributeMaxDynamicSharedMemorySize, SMEM_DYN);
    cudaFuncSetAttribute(mm_k<A_DIRECT, EP_BF_F32>,  cudaFuncAttributeMaxDynamicSharedMemorySize, SMEM_DYN);
    cudaFuncSetAttribute(mm_k<A_DIRECT, EP_GELU_BF>, cudaFuncAttributeMaxDynamicSharedMemorySize, SMEM_DYN);
    cudaFuncSetAttribute(mm_k<A_DIRECT, EP_F32>,     cudaFuncAttributeMaxDynamicSharedMemorySize, SMEM_DYN);
    cudaFuncSetAttribute(mm_k<A_CONCAT, EP_SIG>,     cudaFuncAttributeMaxDynamicSharedMemorySize, SMEM_DYN);
    cudaFuncSetAttribute(mm_k<A_CONCAT, EP_GELU_BF>, cudaFuncAttributeMaxDynamicSharedMemorySize, SMEM_DYN);
    cudaFuncSetAttribute(mm_k<A_DIRECT, EP_FINAL>,   cudaFuncAttributeMaxDynamicSharedMemorySize, SMEM_DYN);

    dim3 wcb(32, 8);

    // ---- conversions ----
    qconv_k<<<2048, 256>>>(queries, qh, ql, (int)NELE);
    wconv_k<<<dim3(32, 7168/32), wcb>>>(fr_w1, w1th, w1tl, 7168, 1024);
    wconv_k<<<dim3(32, 1024/32), wcb>>>(fr_w2, w2th, w2tl, 1024, 1024);
    wconv_k<<<dim3(32, 1024/32), wcb>>>(tc_w1, c1th, c1tl, 1024, 1024);
    wconv4_k<<<dim3(32, 64, 4), wcb>>>(tc_w2, c2th, c2tl, fc_w2, f2th, f2tl,
                                       fc_w1, fcth, fctl, g_w, gwth, gwtl);

    dim3 grid(8, 128), block(256);

    // h1 = gelu(fusion @ fr_w1 + fr_b1)   K=7168 (roll-gathered)
    mm_k<A_ROLL, EP_GELU_BF><<<grid, block, SMEM_DYN>>>(
        qh, ql, nullptr, nullptr, w1th, w1tl, fr_b1, 7168,
        h1h, h1l, nullptr, nullptr, nullptr);
    // x_ring = h1 @ fr_w2 + fr_b2
    mm_k<A_DIRECT, EP_BF_F32><<<grid, block, SMEM_DYN>>>(
        h1h, h1l, nullptr, nullptr, w2th, w2tl, fr_b2, 1024,
        xrh, xrl, xrf, nullptr, nullptr);
    // t1 = gelu(x_ring @ tc_w1 + tc_b1)
    mm_k<A_DIRECT, EP_GELU_BF><<<grid, block, SMEM_DYN>>>(
        xrh, xrl, nullptr, nullptr, c1th, c1tl, tc_b1, 1024,
        t1h, t1l, nullptr, nullptr, nullptr);
    // token_proj = t1 @ tc_w2 + tc_b2
    mm_k<A_DIRECT, EP_F32><<<grid, block, SMEM_DYN>>>(
        t1h, t1l, nullptr, nullptr, c2th, c2tl, tc_b2, 1024,
        nullptr, nullptr, tpf, nullptr, nullptr);
    // weighted = softmax(tp @ centers^T) @ centers
    cluster_k<<<MT / 8, 256>>>(tpf, centers, wth, wtl);
    // gate = sigmoid([xr|wt] @ g_w + g_b)
    mm_k<A_CONCAT, EP_SIG><<<grid, block, SMEM_DYN>>>(
        xrh, xrl, wth, wtl, gwth, gwtl, g_b, 2048,
        nullptr, nullptr, gtf, nullptr, nullptr);
    // h_fc = gelu([xr|wt] @ fc_w1 + fc_b1)
    mm_k<A_CONCAT, EP_GELU_BF><<<grid, block, SMEM_DYN>>>(
        xrh, xrl, wth, wtl, fcth, fctl, fc_b1, 2048,
        hfh, hfl, nullptr, nullptr, nullptr);
    // out = gate * (h_fc @ fc_w2 + fc_b2) + (1-gate) * x_ring
    mm_k<A_DIRECT, EP_FINAL><<<grid, block, SMEM_DYN>>>(
        hfh, hfl, nullptr, nullptr, f2th, f2tl, fc_b2, 1024,
        nullptr, nullptr, out, gtf, xrf);
}